// round 3
// baseline (speedup 1.0000x reference)
#include <cuda_runtime.h>

// Factorization machine, sparse evaluation.
// x[:p] has ~52 nonzeros (1 user, 1 item, 50-item basket). We scan x,
// gather only the needed embedding rows, reduce, finalize in last block.

#define N_USERS 100000
#define M_ITEMS 200000
#define K_DIM   128

// Scratch (zero-initialized at module load; finalizer resets after each run
// so every graph replay starts from zeros -> deterministic).
__device__ float        g_u[K_DIM];
__device__ float        g_t[K_DIM];
__device__ float        g_s[K_DIM];
__device__ float        g_bias;
__device__ float        g_sqsum;
__device__ unsigned int g_count;

__device__ __forceinline__ void accum_row(float* dst, const float* row, float xv) {
    const float4* r4 = reinterpret_cast<const float4*>(row);
    #pragma unroll
    for (int c = 0; c < K_DIM / 4; c++) {
        float4 r = r4[c];
        atomicAdd(&dst[4 * c + 0], xv * r.x);
        atomicAdd(&dst[4 * c + 1], xv * r.y);
        atomicAdd(&dst[4 * c + 2], xv * r.z);
        atomicAdd(&dst[4 * c + 3], xv * r.w);
    }
}

__global__ void fm_sparse_kernel(const float* __restrict__ x,
                                 const float* __restrict__ delta,
                                 const float* __restrict__ w0,
                                 const float* __restrict__ w_bias,
                                 const float* __restrict__ uV,
                                 const float* __restrict__ tV,
                                 const float* __restrict__ bV,
                                 float* __restrict__ out,
                                 int p)
{
    const int n = N_USERS;
    const int m = M_ITEMS;
    const int nvec = p >> 2;  // p divisible by 4

    int tid = blockIdx.x * blockDim.x + threadIdx.x;

    if (tid < nvec) {
        float4 v = reinterpret_cast<const float4*>(x)[tid];
        float vals[4] = {v.x, v.y, v.z, v.w};
        #pragma unroll
        for (int j = 0; j < 4; j++) {
            float xv = vals[j];
            if (xv != 0.0f) {
                int i = tid * 4 + j;
                atomicAdd(&g_bias, xv * w_bias[i]);
                if (i < n) {
                    accum_row(g_u, uV + (size_t)i * K_DIM, xv);
                } else if (i < n + m) {
                    accum_row(g_t, tV + (size_t)(i - n) * K_DIM, xv);
                } else {
                    const float* row = bV + (size_t)(i - n - m) * K_DIM;
                    accum_row(g_s, row, xv);
                    // sq_sum contribution: xv * sum_k row[k]^2
                    const float4* r4 = reinterpret_cast<const float4*>(row);
                    float ss = 0.0f;
                    #pragma unroll
                    for (int c = 0; c < K_DIM / 4; c++) {
                        float4 r = r4[c];
                        ss += r.x * r.x + r.y * r.y + r.z * r.z + r.w * r.w;
                    }
                    atomicAdd(&g_sqsum, xv * ss);
                }
            }
        }
    }

    // ---- last-block-done finalize ----
    __shared__ bool isLast;
    __threadfence();
    __syncthreads();
    if (threadIdx.x == 0) {
        unsigned int old = atomicAdd(&g_count, 1u);
        isLast = (old == gridDim.x - 1);
    }
    __syncthreads();
    if (!isLast) return;

    // 4 dot products over K_DIM=128 lanes: u.t, t.s, u.s, s.s
    __shared__ float red[4][4];   // [quantity][warp]
    int lane = threadIdx.x & 31;
    int warp = threadIdx.x >> 5;

    float ut = 0.f, tb = 0.f, ub = 0.f, ss = 0.f;
    if (threadIdx.x < K_DIM) {
        float u = g_u[threadIdx.x];
        float t = g_t[threadIdx.x];
        float s = g_s[threadIdx.x];
        ut = u * t;
        tb = t * s;
        ub = u * s;
        ss = s * s;
    }
    #pragma unroll
    for (int off = 16; off > 0; off >>= 1) {
        ut += __shfl_down_sync(0xFFFFFFFFu, ut, off);
        tb += __shfl_down_sync(0xFFFFFFFFu, tb, off);
        ub += __shfl_down_sync(0xFFFFFFFFu, ub, off);
        ss += __shfl_down_sync(0xFFFFFFFFu, ss, off);
    }
    if (lane == 0 && warp < 4) {
        red[0][warp] = ut;
        red[1][warp] = tb;
        red[2][warp] = ub;
        red[3][warp] = ss;
    }
    __syncthreads();

    if (threadIdx.x == 0) {
        float s_ut = red[0][0] + red[0][1] + red[0][2] + red[0][3];
        float s_tb = red[1][0] + red[1][1] + red[1][2] + red[1][3];
        float s_ub = red[2][0] + red[2][1] + red[2][2] + red[2][3];
        float s_ss = red[3][0] + red[3][1] + red[3][2] + red[3][3];

        float bs = 0.5f * (s_ss - g_sqsum);
        float y  = w0[0] + g_bias + s_ut + s_tb + bs + s_ub;
        float z  = y * delta[0];
        // -log_sigmoid(z) = softplus(-z), numerically stable
        float r;
        if (z >= 0.0f) r = log1pf(expf(-z));
        else           r = -z + log1pf(expf(z));
        out[0] = r;
    }

    // reset scratch for next (graph-replayed) run
    if (threadIdx.x < K_DIM) {
        g_u[threadIdx.x] = 0.0f;
        g_t[threadIdx.x] = 0.0f;
        g_s[threadIdx.x] = 0.0f;
    }
    if (threadIdx.x == 0) {
        g_bias  = 0.0f;
        g_sqsum = 0.0f;
        g_count = 0u;
    }
}

extern "C" void kernel_launch(void* const* d_in, const int* in_sizes, int n_in,
                              void* d_out, int out_size) {
    const float* x      = (const float*)d_in[0];
    const float* delta  = (const float*)d_in[1];
    // d_in[2] = pmi (unused by reference)
    const float* w0     = (const float*)d_in[3];
    const float* w_bias = (const float*)d_in[4];
    const float* uV     = (const float*)d_in[5];
    const float* tV     = (const float*)d_in[6];
    const float* bV     = (const float*)d_in[7];
    float* out = (float*)d_out;

    int p = in_sizes[4];           // w_bias has p elements (500000)
    int nvec = p / 4;              // float4 elements of x[:p]
    int threads = 256;
    int blocks = (nvec + threads - 1) / threads;

    fm_sparse_kernel<<<blocks, threads>>>(x, delta, w0, w_bias, uV, tV, bV, out, p);
}

// round 5
// speedup vs baseline: 1.7259x; 1.7259x over previous
#include <cuda_runtime.h>

#define N_USERS 100000
#define M_ITEMS 200000
#define K_DIM   128
#define CAP     16384
#define SCAP    2048

// Compacted nonzeros of x[:p]. g_cnt zero-init at load; finalize kernel
// resets it so every graph replay starts clean (deterministic).
__device__ int   g_cnt;
__device__ int   g_idx[CAP];
__device__ float g_val[CAP];

// ---------------- Kernel 1: scan x, compact nonzeros ----------------
__global__ void scan_x_kernel(const float* __restrict__ x, int nvec)
{
    const uint4* x4 = reinterpret_cast<const uint4*>(x);
    int base = blockIdx.x * (blockDim.x * 4) + threadIdx.x;
    #pragma unroll
    for (int u = 0; u < 4; u++) {
        int q = base + u * blockDim.x;   // coalesced per unroll step
        if (q < nvec) {
            uint4 v = x4[q];
            if (v.x | v.y | v.z | v.w) {
                unsigned int bits[4] = {v.x, v.y, v.z, v.w};
                #pragma unroll
                for (int j = 0; j < 4; j++) {
                    if (bits[j] != 0u) {
                        int pos = atomicAdd(&g_cnt, 1);
                        if (pos < CAP) {
                            g_idx[pos] = q * 4 + j;
                            g_val[pos] = __uint_as_float(bits[j]);
                        }
                    }
                }
            }
        }
    }
}

// ---------------- Kernel 2: gather rows, reduce, finalize ----------------
__global__ __launch_bounds__(1024, 1)
void fm_finalize_kernel(const float* __restrict__ delta,
                        const float* __restrict__ w0,
                        const float* __restrict__ w_bias,
                        const float* __restrict__ uV,
                        const float* __restrict__ tV,
                        const float* __restrict__ bV,
                        float* __restrict__ out)
{
    __shared__ int   sh_idx[SCAP];
    __shared__ float sh_val[SCAP];
    __shared__ float s_u[8][K_DIM];
    __shared__ float s_t[8][K_DIM];
    __shared__ float s_s[8][K_DIM];
    __shared__ float s_q[8][K_DIM];
    __shared__ float s_bias[8];
    __shared__ float s_red[5][4];

    int tid = threadIdx.x;
    int cnt = g_cnt;
    if (cnt > CAP) cnt = CAP;
    int c2 = cnt < SCAP ? cnt : SCAP;

    // Stage the nonzero list into SMEM (kills dependent idx->row load chain)
    for (int j = tid; j < c2; j += 1024) {
        sh_idx[j] = g_idx[j];
        sh_val[j] = g_val[j];
    }
    __syncthreads();

    int g = tid >> 7;        // group 0..7
    int k = tid & (K_DIM-1); // k-dim lane 0..127

    float au = 0.f, at = 0.f, as = 0.f, aq = 0.f, ab = 0.f;

    for (int j = g; j < cnt; j += 8) {
        int   i;
        float xv;
        if (j < SCAP) { i = sh_idx[j]; xv = sh_val[j]; }
        else          { i = g_idx[j];  xv = g_val[j];  }

        if (i < N_USERS) {
            au += xv * uV[(size_t)i * K_DIM + k];
        } else if (i < N_USERS + M_ITEMS) {
            at += xv * tV[(size_t)(i - N_USERS) * K_DIM + k];
        } else {
            float r = bV[(size_t)(i - N_USERS - M_ITEMS) * K_DIM + k];
            as += xv * r;
            aq += xv * r * r;
        }
        if (k == 0) ab += xv * w_bias[i];
    }

    s_u[g][k] = au;
    s_t[g][k] = at;
    s_s[g][k] = as;
    s_q[g][k] = aq;
    if (k == 0) s_bias[g] = ab;
    __syncthreads();

    if (tid < K_DIM) {
        float u = 0.f, t = 0.f, s = 0.f, q = 0.f;
        #pragma unroll
        for (int gg = 0; gg < 8; gg++) {
            u += s_u[gg][tid];
            t += s_t[gg][tid];
            s += s_s[gg][tid];
            q += s_q[gg][tid];
        }
        float ut = u * t;
        float tb = t * s;
        float ub = u * s;
        float ss = s * s;
        #pragma unroll
        for (int off = 16; off > 0; off >>= 1) {
            ut += __shfl_down_sync(0xFFFFFFFFu, ut, off);
            tb += __shfl_down_sync(0xFFFFFFFFu, tb, off);
            ub += __shfl_down_sync(0xFFFFFFFFu, ub, off);
            ss += __shfl_down_sync(0xFFFFFFFFu, ss, off);
            q  += __shfl_down_sync(0xFFFFFFFFu, q,  off);
        }
        int lane = tid & 31, w = tid >> 5;
        if (lane == 0) {
            s_red[0][w] = ut;
            s_red[1][w] = tb;
            s_red[2][w] = ub;
            s_red[3][w] = ss;
            s_red[4][w] = q;
        }
    }
    __syncthreads();

    if (tid == 0) {
        float ut = s_red[0][0] + s_red[0][1] + s_red[0][2] + s_red[0][3];
        float tb = s_red[1][0] + s_red[1][1] + s_red[1][2] + s_red[1][3];
        float ub = s_red[2][0] + s_red[2][1] + s_red[2][2] + s_red[2][3];
        float ss = s_red[3][0] + s_red[3][1] + s_red[3][2] + s_red[3][3];
        float q  = s_red[4][0] + s_red[4][1] + s_red[4][2] + s_red[4][3];

        float bias = 0.f;
        #pragma unroll
        for (int gg = 0; gg < 8; gg++) bias += s_bias[gg];

        float bs = 0.5f * (ss - q);
        float y  = w0[0] + bias + ut + tb + bs + ub;
        float z  = y * delta[0];
        // -log_sigmoid(z) = softplus(-z), stable
        float r  = (z >= 0.0f) ? log1pf(expf(-z)) : (-z + log1pf(expf(z)));
        out[0] = r;

        g_cnt = 0;  // restore invariant for next replay
    }
}

extern "C" void kernel_launch(void* const* d_in, const int* in_sizes, int n_in,
                              void* d_out, int out_size) {
    const float* x      = (const float*)d_in[0];
    const float* delta  = (const float*)d_in[1];
    // d_in[2] = pmi (unused by reference)
    const float* w0     = (const float*)d_in[3];
    const float* w_bias = (const float*)d_in[4];
    const float* uV     = (const float*)d_in[5];
    const float* tV     = (const float*)d_in[6];
    const float* bV     = (const float*)d_in[7];
    float* out = (float*)d_out;

    int p    = in_sizes[4];        // 500000
    int nvec = p / 4;              // float4 count (p divisible by 4)

    int threads = 256;
    int per_block = threads * 4;
    int blocks = (nvec + per_block - 1) / per_block;

    scan_x_kernel<<<blocks, threads>>>(x, nvec);
    fm_finalize_kernel<<<1, 1024>>>(delta, w0, w_bias, uV, tV, bV, out);
}

// round 6
// speedup vs baseline: 1.7619x; 1.0208x over previous
#include <cuda_runtime.h>

#define N_USERS 100000
#define M_ITEMS 200000
#define K_DIM   128
#define CAP     16384
#define SCAP    1024
#define GW      16        // gather warps (block = 512 threads)

// Compacted nonzeros of x[:p]. g_cnt zero-init at load; finalize resets it
// so every graph replay starts clean (deterministic).
__device__ int   g_cnt;
__device__ int   g_idx[CAP];
__device__ float g_val[CAP];

// ---------------- Kernel 1: scan x, compact nonzeros ----------------
__global__ void scan_x_kernel(const float* __restrict__ x, int nvec)
{
    const uint4* x4 = reinterpret_cast<const uint4*>(x);
    int base = blockIdx.x * (blockDim.x * 4) + threadIdx.x;
    #pragma unroll
    for (int u = 0; u < 4; u++) {
        int q = base + u * blockDim.x;   // coalesced per unroll step
        if (q < nvec) {
            uint4 v = x4[q];
            if (v.x | v.y | v.z | v.w) {
                unsigned int bits[4] = {v.x, v.y, v.z, v.w};
                #pragma unroll
                for (int j = 0; j < 4; j++) {
                    if (bits[j] != 0u) {
                        int pos = atomicAdd(&g_cnt, 1);
                        if (pos < CAP) {
                            g_idx[pos] = q * 4 + j;
                            g_val[pos] = __uint_as_float(bits[j]);
                        }
                    }
                }
            }
        }
    }
}

// ---------------- Kernel 2: warp-per-nonzero gather + tree reduce ----------------
__global__ __launch_bounds__(512, 1)
void fm_finalize_kernel(const float* __restrict__ delta,
                        const float* __restrict__ w0,
                        const float* __restrict__ w_bias,
                        const float* __restrict__ uV,
                        const float* __restrict__ tV,
                        const float* __restrict__ bV,
                        float* __restrict__ out)
{
    __shared__ int   sh_idx[SCAP];
    __shared__ float sh_val[SCAP];
    __shared__ float s_part[4][GW][K_DIM];   // u,t,s,q partials per warp: 32KB
    __shared__ float s_biasw[GW];
    __shared__ float s_red[5][4];

    const int tid  = threadIdx.x;
    const int warp = tid >> 5;
    const int lane = tid & 31;

    int cnt = g_cnt;
    if (cnt > CAP) cnt = CAP;
    const int c2 = cnt < SCAP ? cnt : SCAP;

    // Stage nonzero list into SMEM
    for (int j = tid; j < c2; j += 512) {
        sh_idx[j] = g_idx[j];
        sh_val[j] = g_val[j];
    }
    __syncthreads();

    float4 au = {0,0,0,0}, at = {0,0,0,0}, as4 = {0,0,0,0}, aq = {0,0,0,0};
    float  ab = 0.f;

    // Chunks of 4 iterations per warp: batch index reads, then batch row loads
    // (all ~52 row gathers in flight together -> one DRAM latency, not 4-7).
    for (int jb = warp; jb < cnt; jb += GW * 4) {
        int   idx[4];
        float xv[4];
        bool  ok[4];
        #pragma unroll
        for (int c = 0; c < 4; c++) {
            int j = jb + GW * c;
            ok[c] = (j < cnt);
            if (ok[c]) {
                if (j < SCAP) { idx[c] = sh_idx[j]; xv[c] = sh_val[j]; }
                else          { idx[c] = g_idx[j];  xv[c] = g_val[j];  }
            } else { idx[c] = 0; xv[c] = 0.f; }
        }

        // Issue all row loads (and lane-0 w_bias loads) before consuming.
        float4 r[4];
        int    cls[4];
        float  wb[4];
        #pragma unroll
        for (int c = 0; c < 4; c++) {
            int i = idx[c];
            const float* rowbase;
            if (i < N_USERS)                 { cls[c] = 0; rowbase = uV + (size_t)i * K_DIM; }
            else if (i < N_USERS + M_ITEMS)  { cls[c] = 1; rowbase = tV + (size_t)(i - N_USERS) * K_DIM; }
            else                             { cls[c] = 2; rowbase = bV + (size_t)(i - N_USERS - M_ITEMS) * K_DIM; }
            r[c]  = reinterpret_cast<const float4*>(rowbase)[lane];
            wb[c] = (lane == 0 && ok[c]) ? w_bias[i] : 0.f;
        }

        #pragma unroll
        for (int c = 0; c < 4; c++) {
            if (!ok[c]) continue;
            float v = xv[c];
            ab += v * wb[c];
            if (cls[c] == 0) {
                au.x += v * r[c].x; au.y += v * r[c].y; au.z += v * r[c].z; au.w += v * r[c].w;
            } else if (cls[c] == 1) {
                at.x += v * r[c].x; at.y += v * r[c].y; at.z += v * r[c].z; at.w += v * r[c].w;
            } else {
                as4.x += v * r[c].x; as4.y += v * r[c].y; as4.z += v * r[c].z; as4.w += v * r[c].w;
                aq.x += v * r[c].x * r[c].x; aq.y += v * r[c].y * r[c].y;
                aq.z += v * r[c].z * r[c].z; aq.w += v * r[c].w * r[c].w;
            }
        }
    }

    // Per-warp partials -> SMEM (float4 stores, conflict-free)
    *reinterpret_cast<float4*>(&s_part[0][warp][lane * 4]) = au;
    *reinterpret_cast<float4*>(&s_part[1][warp][lane * 4]) = at;
    *reinterpret_cast<float4*>(&s_part[2][warp][lane * 4]) = as4;
    *reinterpret_cast<float4*>(&s_part[3][warp][lane * 4]) = aq;
    if (lane == 0) {
        // reduce ab across... ab lives only on lane 0 of each warp
        s_biasw[warp] = ab;
    }
    __syncthreads();

    // 128 threads: sum over GW warps, then 4 dot products + sq_sum via shuffle
    if (tid < K_DIM) {
        float u = 0.f, t = 0.f, s = 0.f, q = 0.f;
        #pragma unroll
        for (int w = 0; w < GW; w++) {
            u += s_part[0][w][tid];
            t += s_part[1][w][tid];
            s += s_part[2][w][tid];
            q += s_part[3][w][tid];
        }
        float ut = u * t;
        float tb = t * s;
        float ub = u * s;
        float ss = s * s;
        #pragma unroll
        for (int off = 16; off > 0; off >>= 1) {
            ut += __shfl_down_sync(0xFFFFFFFFu, ut, off);
            tb += __shfl_down_sync(0xFFFFFFFFu, tb, off);
            ub += __shfl_down_sync(0xFFFFFFFFu, ub, off);
            ss += __shfl_down_sync(0xFFFFFFFFu, ss, off);
            q  += __shfl_down_sync(0xFFFFFFFFu, q,  off);
        }
        if (lane == 0) {
            int w = tid >> 5;
            s_red[0][w] = ut;
            s_red[1][w] = tb;
            s_red[2][w] = ub;
            s_red[3][w] = ss;
            s_red[4][w] = q;
        }
    }
    __syncthreads();

    if (tid == 0) {
        float ut = s_red[0][0] + s_red[0][1] + s_red[0][2] + s_red[0][3];
        float tb = s_red[1][0] + s_red[1][1] + s_red[1][2] + s_red[1][3];
        float ub = s_red[2][0] + s_red[2][1] + s_red[2][2] + s_red[2][3];
        float ss = s_red[3][0] + s_red[3][1] + s_red[3][2] + s_red[3][3];
        float q  = s_red[4][0] + s_red[4][1] + s_red[4][2] + s_red[4][3];

        float bias = 0.f;
        #pragma unroll
        for (int w = 0; w < GW; w++) bias += s_biasw[w];

        float bs = 0.5f * (ss - q);
        float y  = w0[0] + bias + ut + tb + bs + ub;
        float z  = y * delta[0];
        // -log_sigmoid(z) = softplus(-z), stable
        float r  = (z >= 0.0f) ? log1pf(expf(-z)) : (-z + log1pf(expf(z)));
        out[0] = r;

        g_cnt = 0;  // restore invariant for next replay
    }
}

extern "C" void kernel_launch(void* const* d_in, const int* in_sizes, int n_in,
                              void* d_out, int out_size) {
    const float* x      = (const float*)d_in[0];
    const float* delta  = (const float*)d_in[1];
    // d_in[2] = pmi (unused by reference)
    const float* w0     = (const float*)d_in[3];
    const float* w_bias = (const float*)d_in[4];
    const float* uV     = (const float*)d_in[5];
    const float* tV     = (const float*)d_in[6];
    const float* bV     = (const float*)d_in[7];
    float* out = (float*)d_out;

    int p    = in_sizes[4];        // 500000
    int nvec = p / 4;              // float4 count (p divisible by 4)

    int threads = 256;
    int per_block = threads * 4;
    int blocks = (nvec + per_block - 1) / per_block;

    scan_x_kernel<<<blocks, threads>>>(x, nvec);
    fm_finalize_kernel<<<1, 512>>>(delta, w0, w_bias, uV, tV, bV, out);
}